// round 7
// baseline (speedup 1.0000x reference)
#include <cuda_runtime.h>
#include <math.h>

// Problem constants
#define B_  128
#define T_  512
#define I_  300
#define H_  256
#define G4_ 1024  // 4*H

typedef unsigned long long ull;

// ---------------- scratch (device globals; no allocation allowed) ----------
__device__ float g_xp[(size_t)T_ * B_ * G4_];   // forward projections, [t][b][g] (256 MB)
__device__ float g_xpb[B_ * G4_];               // backward proj at t = T-1, [b][g]
__device__ float g_hst[2 * B_ * H_];            // ping-pong h, pair-packed [buf][bpair][k] float2
__device__ float g_hb[B_ * H_];                 // backward final h [b][h]
__device__ unsigned int g_flags[128];           // per-CTA step flags [btile*32 + htile]

// ---------------- f32x2 helpers -------------------------------------------
__device__ __forceinline__ void fma2(ull& d, ull a, ull b) {
    asm("fma.rn.f32x2 %0, %1, %2, %0;" : "+l"(d) : "l"(a), "l"(b));
}
__device__ __forceinline__ ull dup2(float a) {
    ull r; asm("mov.b64 %0, {%1, %1};" : "=l"(r) : "f"(a)); return r;
}
__device__ __forceinline__ float2 unpk(ull v) {
    float2 f; asm("mov.b64 {%0, %1}, %2;" : "=f"(f.x), "=f"(f.y) : "l"(v)); return f;
}
__device__ __forceinline__ float sigf(float x) { return 1.0f / (1.0f + __expf(-x)); }

// ---------------- init: zero h buffer 0 + flags (every replay) -------------
__global__ void init_k() {
    int i = blockIdx.x * blockDim.x + threadIdx.x;
    if (i < B_ * H_) g_hst[i] = 0.0f;
    if (i < 128) g_flags[i] = 0u;
}

// ---------------- SGEMM: C = A * B[N,K]^T + bias[N] ------------------------
// BM=BN=128, BK=8, 256 threads, 8x8 per thread, packed f32x2 math.
// tmajor=0: A row r = (mBase + r), pitch lda; C row = mBase + r.
// tmajor=1: tile = all 128 b at t = blockIdx.y; A row = b*T_ + t (pitch I_);
//           C row = t*128 + b. Both: C row-major pitch G4_ (coalesced stores).
__global__ __launch_bounds__(256, 2) void sgemm_tn(
    const float* __restrict__ A, int lda,
    const float* __restrict__ Bm,  // ldb = K
    const float* __restrict__ bias,
    float* __restrict__ C, int K, int tmajor)
{
    __shared__ float As[8][128];
    __shared__ float Bs[8][128];

    int tid = threadIdx.x;
    int tx = tid & 15, ty = tid >> 4;
    int by = blockIdx.y;
    int mBase = by * 128;
    int nBase = blockIdx.x * 128;

    int lr = tid >> 1;         // 0..127 (row within tile)
    int lc = (tid & 1) * 4;    // 0 or 4 (k sub-col)
    size_t arow = tmajor ? ((size_t)lr * T_ + by) : ((size_t)mBase + lr);
    const float* Aptr = A + arow * (tmajor ? (size_t)I_ : (size_t)lda);
    const float* Bptr = Bm + (size_t)(nBase + lr) * K;

    ull acc[8][4];
#pragma unroll
    for (int i = 0; i < 8; ++i)
#pragma unroll
        for (int j = 0; j < 4; ++j) acc[i][j] = 0ull;

    int ktiles = (K + 7) / 8;
    for (int kt = 0; kt < ktiles; ++kt) {
        int k0 = kt * 8;
        float4 av = make_float4(0.f, 0.f, 0.f, 0.f);
        float4 bv = make_float4(0.f, 0.f, 0.f, 0.f);
        if (k0 + lc < K) av = *reinterpret_cast<const float4*>(Aptr + k0 + lc);
        if (k0 + lc < K) bv = *reinterpret_cast<const float4*>(Bptr + k0 + lc);
        __syncthreads();
        As[lc + 0][lr] = av.x; As[lc + 1][lr] = av.y;
        As[lc + 2][lr] = av.z; As[lc + 3][lr] = av.w;
        Bs[lc + 0][lr] = bv.x; Bs[lc + 1][lr] = bv.y;
        Bs[lc + 2][lr] = bv.z; Bs[lc + 3][lr] = bv.w;
        __syncthreads();

#pragma unroll
        for (int kk = 0; kk < 8; ++kk) {
            float4 a0 = *reinterpret_cast<const float4*>(&As[kk][ty * 4]);
            float4 a1 = *reinterpret_cast<const float4*>(&As[kk][64 + ty * 4]);
            ulonglong2 b0 = *reinterpret_cast<const ulonglong2*>(&Bs[kk][tx * 4]);
            ulonglong2 b1 = *reinterpret_cast<const ulonglong2*>(&Bs[kk][64 + tx * 4]);
            float aa[8] = {a0.x, a0.y, a0.z, a0.w, a1.x, a1.y, a1.z, a1.w};
            ull bb[4] = {b0.x, b0.y, b1.x, b1.y};
#pragma unroll
            for (int i = 0; i < 8; ++i) {
                ull ad = dup2(aa[i]);
#pragma unroll
                for (int j = 0; j < 4; ++j) fma2(acc[i][j], ad, bb[j]);
            }
        }
    }

    float4 bias0 = *reinterpret_cast<const float4*>(&bias[nBase + tx * 4]);
    float4 bias1 = *reinterpret_cast<const float4*>(&bias[nBase + 64 + tx * 4]);
#pragma unroll
    for (int i = 0; i < 8; ++i) {
        int mlocal = (i < 4) ? (ty * 4 + i) : (64 + ty * 4 + (i - 4));
        size_t crow = (size_t)mBase + mlocal;  // same formula both modes
        float2 c0 = unpk(acc[i][0]);
        float2 c1 = unpk(acc[i][1]);
        float2 c2 = unpk(acc[i][2]);
        float2 c3 = unpk(acc[i][3]);
        float* p = C + crow * G4_ + nBase;
        *reinterpret_cast<float4*>(p + tx * 4) =
            make_float4(c0.x + bias0.x, c0.y + bias0.y, c1.x + bias0.z, c1.y + bias0.w);
        *reinterpret_cast<float4*>(p + 64 + tx * 4) =
            make_float4(c2.x + bias1.x, c2.y + bias1.y, c3.x + bias1.z, c3.y + bias1.w);
    }
}

// ---------------- backward direction: single LSTM step from zero state -----
__global__ void bstep_k() {
    int idx = blockIdx.x * 256 + threadIdx.x;
    int b = idx >> 8, h = idx & 255;
    const float* r = g_xpb + (size_t)b * G4_;
    float ig = sigf(r[h]);
    float gg = tanhf(r[512 + h]);
    float og = sigf(r[768 + h]);
    float c = ig * gg;
    g_hb[idx] = og * tanhf(c);
}

// ---------------- persistent forward recurrence ----------------------------
// 128 CTAs x 256 threads. CTA = (btile 0..3) x (htile 0..31).
// Warp lanes: hc = lane&7 (8 gate-cols), lb = lane>>3 (4 bpairs).
// Warp = wg(bp group 0..3) x kh(k half). Thread: 4 gates x 1 bpair, d=128.
// Crossbar per 2k per warp: h 64B-dedup (1cyc) + 4x w 128B full-rate (4cyc).
#define WDS      258                      // float2 stride per row
#define OFF_WD   0                        // 32*258*8 = 66048
#define OFF_HS   66048                    // 16*258*8 = 33024
#define OFF_RED  99072                    // 128*4*8 = 4096
#define SMEM_TOT 103168

__global__ __launch_bounds__(256, 1) void lstm_fwd(const float* __restrict__ Whh)
{
    extern __shared__ char smem[];
    float2* Wd  = reinterpret_cast<float2*>(smem + OFF_WD);
    float2* Hs  = reinterpret_cast<float2*>(smem + OFF_HS);
    ull*    Red = reinterpret_cast<ull*>(smem + OFF_RED);

    int tid = threadIdx.x;
    int wid = tid >> 5, lane = tid & 31;
    int kh = wid >> 2;            // k half
    int wg = wid & 3;             // bp group
    int hc = lane & 7;            // gate-col within htile
    int lb = lane >> 3;           // 0..3
    int bp = wg * 4 + lb;         // local bpair 0..15
    int cta = blockIdx.x;
    int btile = cta & 3;
    int htile = cta >> 2;
    int bpg = btile * 16 + bp;    // global bpair 0..63
    int hcg = htile * 8 + hc;     // global gate-col 0..255

    // load W_hh rows (32 gate-rows of this htile), dup'd into f32x2
    for (int idx = tid; idx < 32 * 256; idx += 256) {
        int row = idx >> 8;              // 0..31 = g*8 + hcr
        int k   = idx & 255;
        int g   = row >> 3, hcr = row & 7;
        float w = Whh[(size_t)(g * 256 + htile * 8 + hcr) * 256 + k];
        Wd[row * WDS + k] = make_float2(w, w);
    }

    float2 c01 = make_float2(0.f, 0.f);  // cell state for (b0,b1), kh==0 only
    const volatile unsigned* myflags = g_flags + btile * 32;

    for (int t = 0; t < T_; ++t) {
        // A) xp prefetch (epilogue threads), independent of sync
        float xv0[4], xv1[4];
        if (tid < 128) {
            const float* p0 = g_xp + ((size_t)t * 128 + bpg * 2) * G4_ + hcg;
#pragma unroll
            for (int g = 0; g < 4; ++g) {
                xv0[g] = __ldg(p0 + g * 256);
                xv1[g] = __ldg(p0 + g * 256 + G4_);
            }
        }

        // B) wait for the 32 producers of this btile to finish step t-1
        if (t > 0 && tid < 32) {
            while (myflags[tid] < (unsigned)t) { }
        }
        __syncthreads();

        // C) stage h (pair-packed, 32KB contiguous) into smem, coalesced
        {
            const float4* src = reinterpret_cast<const float4*>(
                g_hst + (t & 1) * (B_ * H_) + btile * 8192);
#pragma unroll
            for (int j = 0; j < 8; ++j) {
                int idx = tid + j * 256;           // float4 index 0..2047
                float4 v = __ldcg(src + idx);
                int sbp = idx >> 7;                // 128 float4 per bpair row
                int pos = (idx & 127) * 2;         // float2 offset
                *reinterpret_cast<float4*>(Hs + sbp * WDS + pos) = v;
            }
        }
        __syncthreads();

        // D) k loop: 128 k per thread, 2 k/iter; 1 h + 4 w loads + 8 fma2
        ull a_i = 0ull, a_f = 0ull, a_g = 0ull, a_o = 0ull;
        const ulonglong2* hp = reinterpret_cast<const ulonglong2*>(Hs + bp * WDS) + kh * 64;
        const ulonglong2* w0 = reinterpret_cast<const ulonglong2*>(Wd + (hc     ) * WDS) + kh * 64;
        const ulonglong2* w1 = reinterpret_cast<const ulonglong2*>(Wd + (8  + hc) * WDS) + kh * 64;
        const ulonglong2* w2 = reinterpret_cast<const ulonglong2*>(Wd + (16 + hc) * WDS) + kh * 64;
        const ulonglong2* w3 = reinterpret_cast<const ulonglong2*>(Wd + (24 + hc) * WDS) + kh * 64;
#pragma unroll 16
        for (int it = 0; it < 64; ++it) {
            ulonglong2 hv = hp[it];
            ulonglong2 wa = w0[it]; fma2(a_i, hv.x, wa.x); fma2(a_i, hv.y, wa.y);
            ulonglong2 wb = w1[it]; fma2(a_f, hv.x, wb.x); fma2(a_f, hv.y, wb.y);
            ulonglong2 wc = w2[it]; fma2(a_g, hv.x, wc.x); fma2(a_g, hv.y, wc.y);
            ulonglong2 wd = w3[it]; fma2(a_o, hv.x, wd.x); fma2(a_o, hv.y, wd.y);
        }

        // E) combine k halves
        if (kh == 1) {
            ull* rp = Red + (size_t)(tid - 128) * 4;
            rp[0] = a_i; rp[1] = a_f; rp[2] = a_g; rp[3] = a_o;
        }
        __syncthreads();
        if (tid < 128) {
            ull* rp = Red + (size_t)tid * 4;
            float2 si = unpk(a_i), sf = unpk(a_f), sg = unpk(a_g), so = unpk(a_o);
            float2 q;
            q = unpk(rp[0]); si.x += q.x; si.y += q.y;
            q = unpk(rp[1]); sf.x += q.x; sf.y += q.y;
            q = unpk(rp[2]); sg.x += q.x; sg.y += q.y;
            q = unpk(rp[3]); so.x += q.x; so.y += q.y;

            float* hw = g_hst + ((t + 1) & 1) * (B_ * H_);

            float I0 = sigf(si.x + xv0[0]), F0 = sigf(sf.x + xv0[1]);
            float G0 = tanhf(sg.x + xv0[2]), O0 = sigf(so.x + xv0[3]);
            c01.x = F0 * c01.x + I0 * G0;
            float h0 = O0 * tanhf(c01.x);

            float I1 = sigf(si.y + xv1[0]), F1 = sigf(sf.y + xv1[1]);
            float G1 = tanhf(sg.y + xv1[2]), O1 = sigf(so.y + xv1[3]);
            c01.y = F1 * c01.y + I1 * G1;
            float h1 = O1 * tanhf(c01.y);

            *reinterpret_cast<float2*>(hw + (size_t)bpg * 512 + hcg * 2) = make_float2(h0, h1);
        }

        // F) publish
        __syncthreads();
        if (t < T_ - 1 && tid == 0) {
            __threadfence();
            *((volatile unsigned*)&g_flags[btile * 32 + htile]) = (unsigned)(t + 1);
        }
    }
}

// ---------------- final linear: out = [hf, hb] @ W_lin^T + b_lin -----------
__global__ void final_k(const float* __restrict__ Wl, const float* __restrict__ bl,
                        float* __restrict__ out)
{
    __shared__ float s0[8], s1[8];
    int b = blockIdx.x, h = threadIdx.x;   // 256 threads
    // forward final h is in pair-packed buffer 0: [bpair][k] float2
    float hf = g_hst[(size_t)(b >> 1) * 512 + h * 2 + (b & 1)];
    float hb = g_hb[(size_t)b * 256 + h];
    float p0 = hf * Wl[h]       + hb * Wl[256 + h];
    float p1 = hf * Wl[512 + h] + hb * Wl[768 + h];
#pragma unroll
    for (int o = 16; o; o >>= 1) {
        p0 += __shfl_down_sync(0xffffffffu, p0, o);
        p1 += __shfl_down_sync(0xffffffffu, p1, o);
    }
    if ((h & 31) == 0) { s0[h >> 5] = p0; s1[h >> 5] = p1; }
    __syncthreads();
    if (h == 0) {
        float a = 0.f, c = 0.f;
#pragma unroll
        for (int i = 0; i < 8; ++i) { a += s0[i]; c += s1[i]; }
        out[b * 2 + 0] = a + bl[0];
        out[b * 2 + 1] = c + bl[1];
    }
}

// ---------------- host entry ----------------------------------------------
extern "C" void kernel_launch(void* const* d_in, const int* in_sizes, int n_in,
                              void* d_out, int out_size)
{
    const float* x    = (const float*)d_in[0];
    const float* Wihf = (const float*)d_in[1];
    const float* Whhf = (const float*)d_in[2];
    const float* bf   = (const float*)d_in[3];
    const float* Wihb = (const float*)d_in[4];
    const float* bb   = (const float*)d_in[6];
    const float* Wl   = (const float*)d_in[7];
    const float* bl   = (const float*)d_in[8];
    float* out = (float*)d_out;

    void *xp_p = nullptr, *xpb_p = nullptr;
    cudaGetSymbolAddress(&xp_p, g_xp);
    cudaGetSymbolAddress(&xpb_p, g_xpb);

    static bool attr_set = false;
    if (!attr_set) {
        cudaFuncSetAttribute(lstm_fwd, cudaFuncAttributeMaxDynamicSharedMemorySize, SMEM_TOT);
        attr_set = true;
    }

    // 1) zero h buffer 0 + flags
    init_k<<<128, 256>>>();
    // 2) xp_f = x @ W_ih_f^T + b_f, t-major -> [t][b][g], coalesced stores
    sgemm_tn<<<dim3(8, 512), 256>>>(x, I_, Wihf, bf, (float*)xp_p, I_, 1);
    // 3) xp_b at t = T-1 only (row-major [b][g])
    sgemm_tn<<<dim3(8, 1), 256>>>(x + (size_t)(T_ - 1) * I_, T_ * I_, Wihb, bb,
                                  (float*)xpb_p, I_, 0);
    // 4) backward direction = one LSTM step
    bstep_k<<<128, 256>>>();
    // 5) forward recurrence (persistent, 512 steps, flag-based sync)
    lstm_fwd<<<128, 256, SMEM_TOT>>>(Whhf);
    // 6) final linear
    final_k<<<128, 256>>>(Wl, bl, out);
}

// round 9
// speedup vs baseline: 1.1964x; 1.1964x over previous
#include <cuda_runtime.h>
#include <math.h>

// Problem constants
#define B_  128
#define T_  512
#define I_  300
#define H_  256
#define G4_ 1024  // 4*H

typedef unsigned long long ull;

// ---------------- scratch (device globals; no allocation allowed) ----------
__device__ float g_xp[(size_t)T_ * B_ * G4_];   // forward projections, [t][b][g] (256 MB)
__device__ float g_xpb[B_ * G4_];               // backward proj at t = T-1, [b][g]
__device__ float g_hst[2 * B_ * H_];            // ping-pong h, pair-packed [buf][bpair][k] float2
__device__ float g_hb[B_ * H_];                 // backward final h [b][h]
__device__ unsigned int g_flags[128];           // per-CTA step flags [btile*32 + htile]

// ---------------- f32x2 helpers -------------------------------------------
__device__ __forceinline__ void fma2(ull& d, ull a, ull b) {
    asm("fma.rn.f32x2 %0, %1, %2, %0;" : "+l"(d) : "l"(a), "l"(b));
}
__device__ __forceinline__ ull dup2(float a) {
    ull r; asm("mov.b64 %0, {%1, %1};" : "=l"(r) : "f"(a)); return r;
}
__device__ __forceinline__ float2 unpk(ull v) {
    float2 f; asm("mov.b64 {%0, %1}, %2;" : "=f"(f.x), "=f"(f.y) : "l"(v)); return f;
}
__device__ __forceinline__ float sigf(float x) { return 1.0f / (1.0f + __expf(-x)); }

// release-store / acquire-load for the flag protocol (no MEMBAR.GPU/L1 flush)
__device__ __forceinline__ void st_release_u32(unsigned* p, unsigned v) {
    asm volatile("st.release.gpu.global.u32 [%0], %1;" :: "l"(p), "r"(v) : "memory");
}
__device__ __forceinline__ unsigned ld_acquire_u32(const unsigned* p) {
    unsigned v;
    asm volatile("ld.acquire.gpu.global.u32 %0, [%1];" : "=r"(v) : "l"(p) : "memory");
    return v;
}

// ---------------- init: zero h buffer 0 + flags (every replay) -------------
__global__ void init_k() {
    int i = blockIdx.x * blockDim.x + threadIdx.x;
    if (i < B_ * H_) g_hst[i] = 0.0f;
    if (i < 128) g_flags[i] = 0u;
}

// ---------------- SGEMM: C = A * B[N,K]^T + bias[N] ------------------------
// BM=BN=128, BK=8, 256 threads, 8x8 per thread, packed f32x2 math.
// tmajor=0: A row r = (mBase + r), pitch lda; C row = mBase + r.
// tmajor=1: tile = all 128 b at t = blockIdx.y; A row = b*T_ + t (pitch I_);
//           C row = t*128 + b. Both: C row-major pitch G4_ (coalesced stores).
__global__ __launch_bounds__(256, 2) void sgemm_tn(
    const float* __restrict__ A, int lda,
    const float* __restrict__ Bm,  // ldb = K
    const float* __restrict__ bias,
    float* __restrict__ C, int K, int tmajor)
{
    __shared__ float As[8][128];
    __shared__ float Bs[8][128];

    int tid = threadIdx.x;
    int tx = tid & 15, ty = tid >> 4;
    int by = blockIdx.y;
    int mBase = by * 128;
    int nBase = blockIdx.x * 128;

    int lr = tid >> 1;         // 0..127 (row within tile)
    int lc = (tid & 1) * 4;    // 0 or 4 (k sub-col)
    size_t arow = tmajor ? ((size_t)lr * T_ + by) : ((size_t)mBase + lr);
    const float* Aptr = A + arow * (tmajor ? (size_t)I_ : (size_t)lda);
    const float* Bptr = Bm + (size_t)(nBase + lr) * K;

    ull acc[8][4];
#pragma unroll
    for (int i = 0; i < 8; ++i)
#pragma unroll
        for (int j = 0; j < 4; ++j) acc[i][j] = 0ull;

    int ktiles = (K + 7) / 8;
    for (int kt = 0; kt < ktiles; ++kt) {
        int k0 = kt * 8;
        float4 av = make_float4(0.f, 0.f, 0.f, 0.f);
        float4 bv = make_float4(0.f, 0.f, 0.f, 0.f);
        if (k0 + lc < K) av = *reinterpret_cast<const float4*>(Aptr + k0 + lc);
        if (k0 + lc < K) bv = *reinterpret_cast<const float4*>(Bptr + k0 + lc);
        __syncthreads();
        As[lc + 0][lr] = av.x; As[lc + 1][lr] = av.y;
        As[lc + 2][lr] = av.z; As[lc + 3][lr] = av.w;
        Bs[lc + 0][lr] = bv.x; Bs[lc + 1][lr] = bv.y;
        Bs[lc + 2][lr] = bv.z; Bs[lc + 3][lr] = bv.w;
        __syncthreads();

#pragma unroll
        for (int kk = 0; kk < 8; ++kk) {
            float4 a0 = *reinterpret_cast<const float4*>(&As[kk][ty * 4]);
            float4 a1 = *reinterpret_cast<const float4*>(&As[kk][64 + ty * 4]);
            ulonglong2 b0 = *reinterpret_cast<const ulonglong2*>(&Bs[kk][tx * 4]);
            ulonglong2 b1 = *reinterpret_cast<const ulonglong2*>(&Bs[kk][64 + tx * 4]);
            float aa[8] = {a0.x, a0.y, a0.z, a0.w, a1.x, a1.y, a1.z, a1.w};
            ull bb[4] = {b0.x, b0.y, b1.x, b1.y};
#pragma unroll
            for (int i = 0; i < 8; ++i) {
                ull ad = dup2(aa[i]);
#pragma unroll
                for (int j = 0; j < 4; ++j) fma2(acc[i][j], ad, bb[j]);
            }
        }
    }

    float4 bias0 = *reinterpret_cast<const float4*>(&bias[nBase + tx * 4]);
    float4 bias1 = *reinterpret_cast<const float4*>(&bias[nBase + 64 + tx * 4]);
#pragma unroll
    for (int i = 0; i < 8; ++i) {
        int mlocal = (i < 4) ? (ty * 4 + i) : (64 + ty * 4 + (i - 4));
        size_t crow = (size_t)mBase + mlocal;
        float2 c0 = unpk(acc[i][0]);
        float2 c1 = unpk(acc[i][1]);
        float2 c2 = unpk(acc[i][2]);
        float2 c3 = unpk(acc[i][3]);
        float* p = C + crow * G4_ + nBase;
        *reinterpret_cast<float4*>(p + tx * 4) =
            make_float4(c0.x + bias0.x, c0.y + bias0.y, c1.x + bias0.z, c1.y + bias0.w);
        *reinterpret_cast<float4*>(p + 64 + tx * 4) =
            make_float4(c2.x + bias1.x, c2.y + bias1.y, c3.x + bias1.z, c3.y + bias1.w);
    }
}

// ---------------- backward direction: single LSTM step from zero state -----
__global__ void bstep_k() {
    int idx = blockIdx.x * 256 + threadIdx.x;
    int b = idx >> 8, h = idx & 255;
    const float* r = g_xpb + (size_t)b * G4_;
    float ig = sigf(r[h]);
    float gg = tanhf(r[512 + h]);
    float og = sigf(r[768 + h]);
    float c = ig * gg;
    g_hb[idx] = og * tanhf(c);
}

// ---------------- persistent forward recurrence ----------------------------
// 128 CTAs x 256 threads. CTA = (btile 0..3) x (htile 0..31).
// Thread: kq = wid>>1 (k quarter), half = wid&1; hc = lane&7, bq = lane>>3 + half*4.
// Each thread: 2 bpairs x 4 gates, 64 k. Per 2k: 2 h + 4 w LDS, 16 fma2 ->
// crossbar 1280 cyc/step < FMA floor 2048 cyc/step (FMA-pipe-bound).
#define WDS      258                      // float2 stride per row
#define OFF_WD   0                        // 32*258*8 = 66048
#define OFF_HS   66048                    // 16*258*8 = 33024
#define OFF_RED  99072                    // 8*192*8 = 12288
#define SMEM_TOT 111360

__global__ __launch_bounds__(256, 1) void lstm_fwd(const float* __restrict__ Whh)
{
    extern __shared__ char smem[];
    float2* Wd  = reinterpret_cast<float2*>(smem + OFF_WD);
    float2* Hs  = reinterpret_cast<float2*>(smem + OFF_HS);
    ull*    Red = reinterpret_cast<ull*>(smem + OFF_RED);

    int tid = threadIdx.x;
    int wid = tid >> 5, lane = tid & 31;
    int kq = wid >> 1;            // k quarter 0..3
    int half = wid & 1;
    int hc = lane & 7;            // gate-col within htile
    int bq = (lane >> 3) + half * 4;   // 0..7, each = 2 bpairs
    int cta = blockIdx.x;
    int btile = cta & 3;
    int htile = cta >> 2;
    int hcg = htile * 8 + hc;     // global gate-col 0..255
    int bp0 = 2 * bq;             // local bpairs bp0, bp0+1
    int bpg0 = btile * 16 + bp0;  // global bpair
    int b0 = bpg0 * 2;            // global batch base (4 batches)

    // load W_hh rows (32 gate-rows of this htile), dup'd into f32x2
    for (int idx = tid; idx < 32 * 256; idx += 256) {
        int row = idx >> 8;              // 0..31 = g*8 + hcr
        int k   = idx & 255;
        int g   = row >> 3, hcr = row & 7;
        float w = Whh[(size_t)(g * 256 + htile * 8 + hcr) * 256 + k];
        Wd[row * WDS + k] = make_float2(w, w);
    }

    float2 cA = make_float2(0.f, 0.f);   // cell state, bpair0 (tid<64 only)
    float2 cB = make_float2(0.f, 0.f);   // cell state, bpair1
    const unsigned* myflags = g_flags + btile * 32;

    const ulonglong2* hp0 = reinterpret_cast<const ulonglong2*>(Hs + (size_t)bp0 * WDS) + kq * 32;
    const ulonglong2* hp1 = reinterpret_cast<const ulonglong2*>(Hs + (size_t)(bp0 + 1) * WDS) + kq * 32;
    const ulonglong2* w0p = reinterpret_cast<const ulonglong2*>(Wd + (size_t)(hc     ) * WDS) + kq * 32;
    const ulonglong2* w1p = reinterpret_cast<const ulonglong2*>(Wd + (size_t)(8  + hc) * WDS) + kq * 32;
    const ulonglong2* w2p = reinterpret_cast<const ulonglong2*>(Wd + (size_t)(16 + hc) * WDS) + kq * 32;
    const ulonglong2* w3p = reinterpret_cast<const ulonglong2*>(Wd + (size_t)(24 + hc) * WDS) + kq * 32;

    for (int t = 0; t < T_; ++t) {
        // A) xp prefetch (epilogue threads = tid<64), before the sync wait
        float xv[4][4];   // [batch 0..3][gate i,f,g,o]
        if (tid < 64) {
            const float* p0 = g_xp + ((size_t)t * 128 + b0) * G4_ + hcg;
#pragma unroll
            for (int b = 0; b < 4; ++b)
#pragma unroll
                for (int g = 0; g < 4; ++g)
                    xv[b][g] = __ldg(p0 + (size_t)b * G4_ + g * 256);
        }

        // B) wait for the 32 producers of this btile to finish step t-1
        if (t > 0 && tid < 32) {
            while (ld_acquire_u32(&myflags[tid]) < (unsigned)t) { }
        }
        __syncthreads();

        // C) stage h (pair-packed, 32KB contiguous) into smem, coalesced
        {
            const float4* src = reinterpret_cast<const float4*>(
                g_hst + (t & 1) * (B_ * H_) + btile * 8192);
#pragma unroll
            for (int j = 0; j < 8; ++j) {
                int idx = tid + j * 256;           // float4 index 0..2047
                float4 v = __ldcg(src + idx);
                int sbp = idx >> 7;                // 128 float4 per bpair row
                int pos = (idx & 127) * 2;         // float2 offset
                *reinterpret_cast<float4*>(Hs + (size_t)sbp * WDS + pos) = v;
            }
        }
        __syncthreads();

        // D) k loop: 64 k per thread (quarter), 2 k/iter; 2h + 4w loads, 16 fma2
        ull aA[4] = {0ull, 0ull, 0ull, 0ull};   // bpair0: i,f,g,o
        ull aB[4] = {0ull, 0ull, 0ull, 0ull};   // bpair1
#pragma unroll 16
        for (int it = 0; it < 32; ++it) {
            ulonglong2 ha = hp0[it];
            ulonglong2 hb = hp1[it];
            ulonglong2 w;
            w = w0p[it]; fma2(aA[0], ha.x, w.x); fma2(aA[0], ha.y, w.y);
                         fma2(aB[0], hb.x, w.x); fma2(aB[0], hb.y, w.y);
            w = w1p[it]; fma2(aA[1], ha.x, w.x); fma2(aA[1], ha.y, w.y);
                         fma2(aB[1], hb.x, w.x); fma2(aB[1], hb.y, w.y);
            w = w2p[it]; fma2(aA[2], ha.x, w.x); fma2(aA[2], ha.y, w.y);
                         fma2(aB[2], hb.x, w.x); fma2(aB[2], hb.y, w.y);
            w = w3p[it]; fma2(aA[3], ha.x, w.x); fma2(aA[3], ha.y, w.y);
                         fma2(aB[3], hb.x, w.x); fma2(aB[3], hb.y, w.y);
        }

        // E) combine k quarters: kq>0 threads stash, kq==0 (tid<64) reduce
        if (tid >= 64) {
            int idx = (kq - 1) * 64 + (tid & 63);
#pragma unroll
            for (int g = 0; g < 4; ++g) {
                Red[(g    ) * 192 + idx] = aA[g];
                Red[(4 + g) * 192 + idx] = aB[g];
            }
        }
        __syncthreads();
        if (tid < 64) {
            float2 sA[4], sB[4];
#pragma unroll
            for (int g = 0; g < 4; ++g) { sA[g] = unpk(aA[g]); sB[g] = unpk(aB[g]); }
#pragma unroll
            for (int q = 0; q < 3; ++q) {
#pragma unroll
                for (int g = 0; g < 4; ++g) {
                    float2 u = unpk(Red[(g    ) * 192 + q * 64 + tid]);
                    sA[g].x += u.x; sA[g].y += u.y;
                    float2 v = unpk(Red[(4 + g) * 192 + q * 64 + tid]);
                    sB[g].x += v.x; sB[g].y += v.y;
                }
            }

            float2* hw2 = reinterpret_cast<float2*>(g_hst + ((t + 1) & 1) * (B_ * H_));

            // bpair0: batches b0, b0+1
            {
                float I0 = sigf(sA[0].x + xv[0][0]), F0 = sigf(sA[1].x + xv[0][1]);
                float G0 = tanhf(sA[2].x + xv[0][2]), O0 = sigf(sA[3].x + xv[0][3]);
                cA.x = F0 * cA.x + I0 * G0;
                float h0 = O0 * tanhf(cA.x);
                float I1 = sigf(sA[0].y + xv[1][0]), F1 = sigf(sA[1].y + xv[1][1]);
                float G1 = tanhf(sA[2].y + xv[1][2]), O1 = sigf(sA[3].y + xv[1][3]);
                cA.y = F1 * cA.y + I1 * G1;
                float h1 = O1 * tanhf(cA.y);
                hw2[(size_t)bpg0 * 256 + hcg] = make_float2(h0, h1);
            }
            // bpair1: batches b0+2, b0+3
            {
                float I0 = sigf(sB[0].x + xv[2][0]), F0 = sigf(sB[1].x + xv[2][1]);
                float G0 = tanhf(sB[2].x + xv[2][2]), O0 = sigf(sB[3].x + xv[2][3]);
                cB.x = F0 * cB.x + I0 * G0;
                float h2 = O0 * tanhf(cB.x);
                float I1 = sigf(sB[0].y + xv[3][0]), F1 = sigf(sB[1].y + xv[3][1]);
                float G1 = tanhf(sB[2].y + xv[3][2]), O1 = sigf(sB[3].y + xv[3][3]);
                cB.y = F1 * cB.y + I1 * G1;
                float h3 = O1 * tanhf(cB.y);
                hw2[(size_t)(bpg0 + 1) * 256 + hcg] = make_float2(h2, h3);
            }
        }

        // F) publish: bar.sync orders all threads' h STGs; release-store flag
        __syncthreads();
        if (t < T_ - 1 && tid == 0) {
            st_release_u32(&g_flags[btile * 32 + htile], (unsigned)(t + 1));
        }
    }
}

// ---------------- final linear: out = [hf, hb] @ W_lin^T + b_lin -----------
__global__ void final_k(const float* __restrict__ Wl, const float* __restrict__ bl,
                        float* __restrict__ out)
{
    __shared__ float s0[8], s1[8];
    int b = blockIdx.x, h = threadIdx.x;   // 256 threads
    // forward final h is in pair-packed buffer 0: [bpair][k] float2
    float hf = g_hst[(size_t)(b >> 1) * 512 + h * 2 + (b & 1)];
    float hb = g_hb[(size_t)b * 256 + h];
    float p0 = hf * Wl[h]       + hb * Wl[256 + h];
    float p1 = hf * Wl[512 + h] + hb * Wl[768 + h];
#pragma unroll
    for (int o = 16; o; o >>= 1) {
        p0 += __shfl_down_sync(0xffffffffu, p0, o);
        p1 += __shfl_down_sync(0xffffffffu, p1, o);
    }
    if ((h & 31) == 0) { s0[h >> 5] = p0; s1[h >> 5] = p1; }
    __syncthreads();
    if (h == 0) {
        float a = 0.f, c = 0.f;
#pragma unroll
        for (int i = 0; i < 8; ++i) { a += s0[i]; c += s1[i]; }
        out[b * 2 + 0] = a + bl[0];
        out[b * 2 + 1] = c + bl[1];
    }
}

// ---------------- host entry ----------------------------------------------
extern "C" void kernel_launch(void* const* d_in, const int* in_sizes, int n_in,
                              void* d_out, int out_size)
{
    const float* x    = (const float*)d_in[0];
    const float* Wihf = (const float*)d_in[1];
    const float* Whhf = (const float*)d_in[2];
    const float* bf   = (const float*)d_in[3];
    const float* Wihb = (const float*)d_in[4];
    const float* bb   = (const float*)d_in[6];
    const float* Wl   = (const float*)d_in[7];
    const float* bl   = (const float*)d_in[8];
    float* out = (float*)d_out;

    void *xp_p = nullptr, *xpb_p = nullptr;
    cudaGetSymbolAddress(&xp_p, g_xp);
    cudaGetSymbolAddress(&xpb_p, g_xpb);

    static bool attr_set = false;
    if (!attr_set) {
        cudaFuncSetAttribute(lstm_fwd, cudaFuncAttributeMaxDynamicSharedMemorySize, SMEM_TOT);
        attr_set = true;
    }

    // Launch order places lstm_fwd in ncu's captured slot (4th kernel).
    // 1) zero h buffer 0 + flags
    init_k<<<128, 256>>>();
    // 2) xp_f = x @ W_ih_f^T + b_f, t-major -> [t][b][g], coalesced stores
    sgemm_tn<<<dim3(8, 512), 256>>>(x, I_, Wihf, bf, (float*)xp_p, I_, 1);
    // 3) xp_b at t = T-1 only (row-major [b][g])
    sgemm_tn<<<dim3(8, 1), 256>>>(x + (size_t)(T_ - 1) * I_, T_ * I_, Wihb, bb,
                                  (float*)xpb_p, I_, 0);
    // 4) forward recurrence (persistent, 512 steps) — PROFILED SLOT
    lstm_fwd<<<128, 256, SMEM_TOT>>>(Whhf);
    // 5) backward direction = one LSTM step
    bstep_k<<<128, 256>>>();
    // 6) final linear
    final_k<<<128, 256>>>(Wl, bl, out);
}